// round 9
// baseline (speedup 1.0000x reference)
#include <cuda_runtime.h>
#include <cstdint>
#include <cstddef>

#define NE_ 8
#define DIM 2048
#define HIDDEN 7168
#define NTOK 2048

// ---------------- device scratch ----------------
__device__ int   g_cnt[NE_];
__device__ int   g_tok[NE_][NTOK];
__device__ int   g_slotA[NE_][NTOK];
__device__ float g_wt[NE_][NTOK];
__device__ float g_x[(size_t)NTOK * DIM];            // tf32-rounded x
__device__ float g_h[(size_t)NTOK * 2 * HIDDEN];     // tf32-rounded SwiGLU act

// ---------------- helpers ----------------
__device__ __forceinline__ uint32_t smem_u32(const void* p) {
    uint32_t a;
    asm("{ .reg .u64 t; cvta.to.shared.u64 t, %1; cvt.u32.u64 %0, t; }" : "=r"(a) : "l"(p));
    return a;
}
__device__ __forceinline__ unsigned tf32r(unsigned u) {
    unsigned r;
    asm("cvt.rna.tf32.f32 %0, %1;" : "=r"(r) : "r"(u));
    return r;
}
__device__ __forceinline__ float rtf(float v) {       // round value to tf32 grid
    return __uint_as_float(tf32r(__float_as_uint(v)));
}
__device__ __forceinline__ unsigned lds32(uint32_t a) {
    unsigned v;
    asm volatile("ld.shared.b32 %0, [%1];" : "=r"(v) : "r"(a));
    return v;
}
__device__ __forceinline__ void ldsm4(unsigned* r, uint32_t a) {
    asm volatile("ldmatrix.sync.aligned.m8n8.x4.shared.b16 {%0,%1,%2,%3}, [%4];"
                 : "=r"(r[0]), "=r"(r[1]), "=r"(r[2]), "=r"(r[3]) : "r"(a));
}
__device__ __forceinline__ void mma8(float* c, const unsigned* a, unsigned b0, unsigned b1) {
    asm("mma.sync.aligned.m16n8k8.row.col.f32.tf32.tf32.f32 "
        "{%0,%1,%2,%3}, {%4,%5,%6,%7}, {%8,%9}, {%0,%1,%2,%3};"
        : "+f"(c[0]), "+f"(c[1]), "+f"(c[2]), "+f"(c[3])
        : "r"(a[0]), "r"(a[1]), "r"(a[2]), "r"(a[3]), "r"(b0), "r"(b1));
}
#define CPA(dst, src) asm volatile("cp.async.cg.shared.global [%0], [%1], 16;" :: "r"(dst), "l"(src) : "memory")
#define CPC() asm volatile("cp.async.commit_group;" ::: "memory")
#define CPW1() asm volatile("cp.async.wait_group 1;" ::: "memory")
#define CPW0() asm volatile("cp.async.wait_group 0;" ::: "memory")

// ---------------- kernel 0: reset + zero + pre-round x ----------------
__global__ void zero_kernel(float* __restrict__ out, int n) {
    int idx = blockIdx.x * blockDim.x + threadIdx.x;
    if (idx < NE_) g_cnt[idx] = 0;
    for (int i = idx; i < n; i += gridDim.x * blockDim.x) out[i] = 0.f;
}
__global__ void round_x_kernel(const float* __restrict__ x) {
    int i = blockIdx.x * blockDim.x + threadIdx.x;
    const int N = NTOK * DIM;
    for (; i < N; i += gridDim.x * blockDim.x) g_x[i] = rtf(x[i]);
}

// ---------------- kernel 1: gating ----------------
__global__ void gate_kernel(const float* __restrict__ x, const float* __restrict__ Wg) {
    int lane = threadIdx.x & 31;
    int t = blockIdx.x * (blockDim.x >> 5) + (threadIdx.x >> 5);
    if (t >= NTOK) return;
    const float* xr = x + (size_t)t * DIM;
    float acc[NE_];
#pragma unroll
    for (int e = 0; e < NE_; e++) acc[e] = 0.f;
    for (int d = lane; d < DIM; d += 32) {
        float xv = xr[d];
        const float* wr = Wg + d * NE_;
#pragma unroll
        for (int e = 0; e < NE_; e++) acc[e] += xv * wr[e];
    }
#pragma unroll
    for (int e = 0; e < NE_; e++)
#pragma unroll
        for (int s = 16; s > 0; s >>= 1) acc[e] += __shfl_xor_sync(0xffffffffu, acc[e], s);
    if (lane == 0) {
        int b0 = 0;
#pragma unroll
        for (int e = 1; e < NE_; e++) if (acc[e] > acc[b0]) b0 = e;
        int b1 = (b0 == 0) ? 1 : 0;
#pragma unroll
        for (int e = 0; e < NE_; e++) if (e != b0 && acc[e] > acc[b1]) b1 = e;
        float d1 = expf(acc[b1] - acc[b0]);
        float inv = 1.f / (1.f + d1);
        int p0 = atomicAdd(&g_cnt[b0], 1);
        g_tok[b0][p0] = t; g_slotA[b0][p0] = 2 * t;     g_wt[b0][p0] = inv;
        int p1 = atomicAdd(&g_cnt[b1], 1);
        g_tok[b1][p1] = t; g_slotA[b1][p1] = 2 * t + 1; g_wt[b1][p1] = d1 * inv;
    }
}

// ============================================================================
// GEMM1: dual (x@w1, x@w3) + SwiGLU -> g_h.  BM=128, BN=64(x2), BK=32.
// stage: A 128x144B = 18432, B 2x(32x288) = 18432 -> 36864. 3 stages.
// ============================================================================
#define S1 36864
#define KT1 (DIM / 32)

__global__ __launch_bounds__(256)
void gemm1_k(const float* __restrict__ w1, const float* __restrict__ w3) {
    int e = blockIdx.z, Ne = g_cnt[e];
    int m0 = blockIdx.x * 128;
    if (m0 >= Ne) return;
    int n0 = blockIdx.y * 64;

    extern __shared__ __align__(128) char sm[];
    uint32_t sb = smem_u32(sm);
    __shared__ int rtok[128], rslot[128];

    int tid = threadIdx.x, warp = tid >> 5, lane = tid & 31;
    if (tid < 128) {
        int r = m0 + tid;
        rtok[tid]  = (r < Ne) ? g_tok[e][r] : 0;
        rslot[tid] = (r < Ne) ? g_slotA[e][r] : -1;
    }
    __syncthreads();

    // ---- loaders ----
    int am = tid >> 1, ak = tid & 1;                       // A: row, 64B half
    const float* asrc = g_x + (size_t)rtok[am] * DIM + ak * 16;
    uint32_t adst = sb + am * 144 + ak * 64;
    int bmat = tid >> 7, bt = tid & 127;
    int bk = bt >> 2, bq = bt & 3;                         // B: k-row 0..31, 16n chunk
    const float* bsrc = (bmat ? w3 : w1) + (size_t)e * DIM * HIDDEN + n0
                        + (size_t)bk * HIDDEN + bq * 16;
    uint32_t bdst = sb + 18432 + bmat * 9216 + bk * 288 + bq * 64;

    auto fill = [&](int s, int k0) {
        uint32_t so = (uint32_t)s * S1;
        const float* as = asrc + k0;
        CPA(adst + so,      as);
        CPA(adst + so + 16, as + 4);
        CPA(adst + so + 32, as + 8);
        CPA(adst + so + 48, as + 12);
        const float* bs = bsrc + (size_t)k0 * HIDDEN;
        CPA(bdst + so,      bs);
        CPA(bdst + so + 16, bs + 4);
        CPA(bdst + so + 32, bs + 8);
        CPA(bdst + so + 48, bs + 12);
    };

    // ---- mma geometry ----
    int m_base = (warp >> 2) * 64, n_base = (warp & 3) * 16;
    int lrow = (lane & 7) + ((lane >> 3) & 1) * 8;
    uint32_t abase = sb + (m_base + lrow) * 144 + (lane >> 4) * 16;
    uint32_t bcol  = (uint32_t)(n_base + (lane >> 2)) * 4;
    uint32_t brow  = (uint32_t)(lane & 3) * 288;

    float acc1[4][2][4], acc3[4][2][4];
#pragma unroll
    for (int a = 0; a < 4; a++)
#pragma unroll
        for (int b = 0; b < 2; b++)
#pragma unroll
            for (int c = 0; c < 4; c++) { acc1[a][b][c] = 0.f; acc3[a][b][c] = 0.f; }

    fill(0, 0); CPC();
    fill(1, 32); CPC();
    CPW1(); __syncthreads();

    int s = 0, fs = 2;
    for (int kt = 0; kt < KT1; kt++) {
        uint32_t so = (uint32_t)s * S1;
#pragma unroll
        for (int ks = 0; ks < 4; ks++) {
            unsigned a[4][4];
#pragma unroll
            for (int mt = 0; mt < 4; mt++)
                ldsm4(a[mt], abase + so + mt * 2304 + ks * 32);
            uint32_t bb = sb + so + 18432 + ks * 8 * 288 + brow + bcol;
#pragma unroll
            for (int nt = 0; nt < 2; nt++) {
                uint32_t ba = bb + nt * 32;
                unsigned b0 = tf32r(lds32(ba)),        b1 = tf32r(lds32(ba + 4 * 288));
                unsigned c0 = tf32r(lds32(ba + 9216)), c1 = tf32r(lds32(ba + 9216 + 4 * 288));
#pragma unroll
                for (int mt = 0; mt < 4; mt++) {
                    mma8(acc1[mt][nt], a[mt], b0, b1);
                    mma8(acc3[mt][nt], a[mt], c0, c1);
                }
            }
        }
        int nk = kt + 2;
        if (nk < KT1) fill(fs, nk * 32);
        CPC();
        CPW1(); __syncthreads();
        s = (s == 2) ? 0 : s + 1;
        fs = (fs == 2) ? 0 : fs + 1;
    }
    CPW0();

    // epilogue: silu(y1)*y3 -> g_h[slot], pre-rounded to tf32
#pragma unroll
    for (int mt = 0; mt < 4; mt++) {
        int mloc = m_base + mt * 16 + (lane >> 2);
        int s_lo = rslot[mloc], s_hi = rslot[mloc + 8];
#pragma unroll
        for (int nt = 0; nt < 2; nt++) {
            int col = n0 + n_base + nt * 8 + 2 * (lane & 3);
            if (s_lo >= 0) {
                float* hp = g_h + (size_t)s_lo * HIDDEN + col;
                float a0 = acc1[mt][nt][0], a1 = acc1[mt][nt][1];
                hp[0] = rtf(a0 / (1.f + __expf(-a0)) * acc3[mt][nt][0]);
                hp[1] = rtf(a1 / (1.f + __expf(-a1)) * acc3[mt][nt][1]);
            }
            if (s_hi >= 0) {
                float* hp = g_h + (size_t)s_hi * HIDDEN + col;
                float a2 = acc1[mt][nt][2], a3 = acc1[mt][nt][3];
                hp[0] = rtf(a2 / (1.f + __expf(-a2)) * acc3[mt][nt][2]);
                hp[1] = rtf(a3 / (1.f + __expf(-a3)) * acc3[mt][nt][3]);
            }
        }
    }
}

// ============================================================================
// GEMM2: out += wt * (h @ w2).  BM=128, BN=128, BK=32.
// stage: A 18432 + B 32x544 = 17408 -> 35840. 3 stages.
// ============================================================================
#define S2 35840
#define KT2 (HIDDEN / 32)

__global__ __launch_bounds__(256)
void gemm2_k(const float* __restrict__ w2, float* __restrict__ out) {
    int e = blockIdx.z, Ne = g_cnt[e];
    int m0 = blockIdx.x * 128;
    if (m0 >= Ne) return;
    int n0 = blockIdx.y * 128;

    extern __shared__ __align__(128) char sm[];
    uint32_t sb = smem_u32(sm);
    __shared__ int rtok[128], rsl[128];
    __shared__ float rwt[128];

    int tid = threadIdx.x, warp = tid >> 5, lane = tid & 31;
    if (tid < 128) {
        int r = m0 + tid;
        if (r < Ne) { rtok[tid] = g_tok[e][r]; rsl[tid] = g_slotA[e][r]; rwt[tid] = g_wt[e][r]; }
        else        { rtok[tid] = -1; rsl[tid] = 0; rwt[tid] = 0.f; }
    }
    __syncthreads();

    int am = tid >> 1, ak = tid & 1;
    const float* asrc = g_h + (size_t)rsl[am] * HIDDEN + ak * 16;
    uint32_t adst = sb + am * 144 + ak * 64;
    int bk = tid >> 3, bq = tid & 7;                      // k-row 0..31, 16n chunk
    const float* bsrc = w2 + (size_t)e * HIDDEN * DIM + n0 + (size_t)bk * DIM + bq * 16;
    uint32_t bdst = sb + 18432 + bk * 544 + bq * 64;

    auto fill = [&](int s, int k0) {
        uint32_t so = (uint32_t)s * S2;
        const float* as = asrc + k0;
        CPA(adst + so,      as);
        CPA(adst + so + 16, as + 4);
        CPA(adst + so + 32, as + 8);
        CPA(adst + so + 48, as + 12);
        const float* bs = bsrc + (size_t)k0 * DIM;
        CPA(bdst + so,      bs);
        CPA(bdst + so + 16, bs + 4);
        CPA(bdst + so + 32, bs + 8);
        CPA(bdst + so + 48, bs + 12);
    };

    int m_base = (warp >> 2) * 64, n_base = (warp & 3) * 32;
    int lrow = (lane & 7) + ((lane >> 3) & 1) * 8;
    uint32_t abase = sb + (m_base + lrow) * 144 + (lane >> 4) * 16;
    uint32_t bcol  = (uint32_t)(n_base + (lane >> 2)) * 4;
    uint32_t brow  = (uint32_t)(lane & 3) * 544;

    float acc[4][4][4];
#pragma unroll
    for (int a = 0; a < 4; a++)
#pragma unroll
        for (int b = 0; b < 4; b++)
#pragma unroll
            for (int c = 0; c < 4; c++) acc[a][b][c] = 0.f;

    fill(0, 0); CPC();
    fill(1, 32); CPC();
    CPW1(); __syncthreads();

    int s = 0, fs = 2;
    for (int kt = 0; kt < KT2; kt++) {
        uint32_t so = (uint32_t)s * S2;
#pragma unroll
        for (int ks = 0; ks < 4; ks++) {
            unsigned a[4][4];
#pragma unroll
            for (int mt = 0; mt < 4; mt++)
                ldsm4(a[mt], abase + so + mt * 2304 + ks * 32);
            uint32_t bb = sb + so + 18432 + ks * 8 * 544 + brow + bcol;
#pragma unroll
            for (int nt = 0; nt < 4; nt++) {
                uint32_t ba = bb + nt * 32;
                unsigned b0 = tf32r(lds32(ba)), b1 = tf32r(lds32(ba + 4 * 544));
#pragma unroll
                for (int mt = 0; mt < 4; mt++)
                    mma8(acc[mt][nt], a[mt], b0, b1);
            }
        }
        int nk = kt + 2;
        if (nk < KT2) fill(fs, nk * 32);
        CPC();
        CPW1(); __syncthreads();
        s = (s == 2) ? 0 : s + 1;
        fs = (fs == 2) ? 0 : fs + 1;
    }
    CPW0();

    // epilogue: out[token] += wt * acc
#pragma unroll
    for (int mt = 0; mt < 4; mt++) {
        int mloc = m_base + mt * 16 + (lane >> 2);
        int t_lo = rtok[mloc], t_hi = rtok[mloc + 8];
        float w_lo = rwt[mloc], w_hi = rwt[mloc + 8];
#pragma unroll
        for (int nt = 0; nt < 4; nt++) {
            int col = n0 + n_base + nt * 8 + 2 * (lane & 3);
            if (t_lo >= 0) {
                atomicAdd(&out[(size_t)t_lo * DIM + col],     w_lo * acc[mt][nt][0]);
                atomicAdd(&out[(size_t)t_lo * DIM + col + 1], w_lo * acc[mt][nt][1]);
            }
            if (t_hi >= 0) {
                atomicAdd(&out[(size_t)t_hi * DIM + col],     w_hi * acc[mt][nt][2]);
                atomicAdd(&out[(size_t)t_hi * DIM + col + 1], w_hi * acc[mt][nt][3]);
            }
        }
    }
}

// ---------------- launch ----------------
extern "C" void kernel_launch(void* const* d_in, const int* in_sizes, int n_in,
                              void* d_out, int out_size) {
    const float* x  = (const float*)d_in[0];
    const float* Wg = (const float*)d_in[1];
    const float* w1 = (const float*)d_in[2];
    const float* w3 = (const float*)d_in[3];
    const float* w2 = (const float*)d_in[4];
    float* out = (float*)d_out;

    cudaFuncSetAttribute(gemm1_k, cudaFuncAttributeMaxDynamicSharedMemorySize, 3 * S1);
    cudaFuncSetAttribute(gemm2_k, cudaFuncAttributeMaxDynamicSharedMemorySize, 3 * S2);

    zero_kernel<<<1024, 256>>>(out, out_size);
    round_x_kernel<<<1024, 256>>>(x);
    gate_kernel<<<NTOK / 8, 256>>>(x, Wg);

    dim3 g1(NTOK / 128, HIDDEN / 64, NE_);   // (16, 112, 8)
    gemm1_k<<<g1, 256, 3 * S1>>>(w1, w3);

    dim3 g2(NTOK / 128, DIM / 128, NE_);     // (16, 16, 8)
    gemm2_k<<<g2, 256, 3 * S2>>>(w2, out);
}

// round 10
// speedup vs baseline: 1.3758x; 1.3758x over previous
#include <cuda_runtime.h>
#include <cstdint>
#include <cstddef>

#define NE_ 8
#define DIM 2048
#define HIDDEN 7168
#define NTOK 2048

// ---------------- device scratch ----------------
__device__ int   g_cnt[NE_];
__device__ int   g_tok[NE_][NTOK];
__device__ int   g_slotA[NE_][NTOK];
__device__ float g_wt[NE_][NTOK];
__device__ float g_x[(size_t)NTOK * DIM];            // tf32-rounded x
__device__ float g_h[(size_t)NTOK * 2 * HIDDEN];     // tf32-rounded SwiGLU act

// ---------------- helpers ----------------
__device__ __forceinline__ uint32_t smem_u32(const void* p) {
    uint32_t a;
    asm("{ .reg .u64 t; cvta.to.shared.u64 t, %1; cvt.u32.u64 %0, t; }" : "=r"(a) : "l"(p));
    return a;
}
__device__ __forceinline__ unsigned tf32r(unsigned u) {
    unsigned r;
    asm("cvt.rna.tf32.f32 %0, %1;" : "=r"(r) : "r"(u));
    return r;
}
__device__ __forceinline__ float rtf(float v) {
    return __uint_as_float(tf32r(__float_as_uint(v)));
}
__device__ __forceinline__ unsigned lds32(uint32_t a) {
    unsigned v;
    asm volatile("ld.shared.b32 %0, [%1];" : "=r"(v) : "r"(a));
    return v;
}
__device__ __forceinline__ void ldsm4(unsigned* r, uint32_t a) {
    asm volatile("ldmatrix.sync.aligned.m8n8.x4.shared.b16 {%0,%1,%2,%3}, [%4];"
                 : "=r"(r[0]), "=r"(r[1]), "=r"(r[2]), "=r"(r[3]) : "r"(a));
}
__device__ __forceinline__ void mma8(float* c, const unsigned* a, unsigned b0, unsigned b1) {
    asm("mma.sync.aligned.m16n8k8.row.col.f32.tf32.tf32.f32 "
        "{%0,%1,%2,%3}, {%4,%5,%6,%7}, {%8,%9}, {%0,%1,%2,%3};"
        : "+f"(c[0]), "+f"(c[1]), "+f"(c[2]), "+f"(c[3])
        : "r"(a[0]), "r"(a[1]), "r"(a[2]), "r"(a[3]), "r"(b0), "r"(b1));
}
#define CPA(dst, src) asm volatile("cp.async.cg.shared.global [%0], [%1], 16;" :: "r"(dst), "l"(src) : "memory")
#define CPC() asm volatile("cp.async.commit_group;" ::: "memory")
#define CPW1() asm volatile("cp.async.wait_group 1;" ::: "memory")
#define CPW0() asm volatile("cp.async.wait_group 0;" ::: "memory")

// ---------------- kernel 0: reset + zero + pre-round x ----------------
__global__ void zero_kernel(float* __restrict__ out, int n) {
    int idx = blockIdx.x * blockDim.x + threadIdx.x;
    if (idx < NE_) g_cnt[idx] = 0;
    for (int i = idx; i < n; i += gridDim.x * blockDim.x) out[i] = 0.f;
}
__global__ void round_x_kernel(const float* __restrict__ x) {
    int i = blockIdx.x * blockDim.x + threadIdx.x;
    const int N = NTOK * DIM;
    for (; i < N; i += gridDim.x * blockDim.x) g_x[i] = rtf(x[i]);
}

// ---------------- kernel 1: gating ----------------
__global__ void gate_kernel(const float* __restrict__ x, const float* __restrict__ Wg) {
    int lane = threadIdx.x & 31;
    int t = blockIdx.x * (blockDim.x >> 5) + (threadIdx.x >> 5);
    if (t >= NTOK) return;
    const float* xr = x + (size_t)t * DIM;
    float acc[NE_];
#pragma unroll
    for (int e = 0; e < NE_; e++) acc[e] = 0.f;
    for (int d = lane; d < DIM; d += 32) {
        float xv = xr[d];
        const float* wr = Wg + d * NE_;
#pragma unroll
        for (int e = 0; e < NE_; e++) acc[e] += xv * wr[e];
    }
#pragma unroll
    for (int e = 0; e < NE_; e++)
#pragma unroll
        for (int s = 16; s > 0; s >>= 1) acc[e] += __shfl_xor_sync(0xffffffffu, acc[e], s);
    if (lane == 0) {
        int b0 = 0;
#pragma unroll
        for (int e = 1; e < NE_; e++) if (acc[e] > acc[b0]) b0 = e;
        int b1 = (b0 == 0) ? 1 : 0;
#pragma unroll
        for (int e = 0; e < NE_; e++) if (e != b0 && acc[e] > acc[b1]) b1 = e;
        float d1 = expf(acc[b1] - acc[b0]);
        float inv = 1.f / (1.f + d1);
        int p0 = atomicAdd(&g_cnt[b0], 1);
        g_tok[b0][p0] = t; g_slotA[b0][p0] = 2 * t;     g_wt[b0][p0] = inv;
        int p1 = atomicAdd(&g_cnt[b1], 1);
        g_tok[b1][p1] = t; g_slotA[b1][p1] = 2 * t + 1; g_wt[b1][p1] = d1 * inv;
    }
}

// ============================================================================
// GEMM1: dual (x@w1, x@w3) + SwiGLU -> g_h.
// BM=128, BN=64 (dual), BK=16, 512 threads (16 warps, 32x16x2 warp tiles).
// stage: A 128x80 = 10240, B 2x(16x288) = 9216 -> 19456. 3 stages.
// ============================================================================
#define S1 19456
#define KT1 (DIM / 16)

__global__ __launch_bounds__(512, 2)
void gemm1_k(const float* __restrict__ w1, const float* __restrict__ w3) {
    int e = blockIdx.z, Ne = g_cnt[e];
    int m0 = blockIdx.x * 128;
    if (m0 >= Ne) return;
    int n0 = blockIdx.y * 64;

    extern __shared__ __align__(128) char sm[];
    uint32_t sb = smem_u32(sm);
    __shared__ int rtok[128], rslot[128];

    int tid = threadIdx.x, warp = tid >> 5, lane = tid & 31;
    if (tid < 128) {
        int r = m0 + tid;
        rtok[tid]  = (r < Ne) ? g_tok[e][r] : 0;
        rslot[tid] = (r < Ne) ? g_slotA[e][r] : -1;
    }
    __syncthreads();

    // ---- loaders (1 CPA each for A and B per stage) ----
    int am = tid >> 2, aq = tid & 3;
    const float* asrc = g_x + (size_t)rtok[am] * DIM + aq * 4;
    uint32_t adst = sb + am * 80 + aq * 16;
    int bmat = tid >> 8, bt = tid & 255;
    int br = bt >> 4, bq = bt & 15;
    const float* bsrc = (bmat ? w3 : w1) + (size_t)e * DIM * HIDDEN + n0
                        + (size_t)br * HIDDEN + bq * 4;
    uint32_t bdst = sb + 10240 + bmat * 4608 + br * 288 + bq * 16;

    auto fill = [&](int s, int k0) {
        uint32_t so = (uint32_t)s * S1;
        CPA(adst + so, asrc + k0);
        CPA(bdst + so, bsrc + (size_t)k0 * HIDDEN);
    };

    // ---- mma geometry: 4m x 4n warp grid, warp tile 32x16 (x2 matrices) ----
    int m_base = (warp >> 2) * 32, n_base = (warp & 3) * 16;
    int lrow = (lane & 7) + ((lane >> 3) & 1) * 8;
    uint32_t abase = sb + (m_base + lrow) * 80 + (lane >> 4) * 16;
    uint32_t bcol  = (uint32_t)(n_base + (lane >> 2)) * 4;
    uint32_t brow  = (uint32_t)(lane & 3) * 288;

    float acc1[2][2][4], acc3[2][2][4];
#pragma unroll
    for (int a = 0; a < 2; a++)
#pragma unroll
        for (int b = 0; b < 2; b++)
#pragma unroll
            for (int c = 0; c < 4; c++) { acc1[a][b][c] = 0.f; acc3[a][b][c] = 0.f; }

    fill(0, 0); CPC();
    fill(1, 16); CPC();
    CPW1(); __syncthreads();

    int s = 0, fs = 2;
    for (int kt = 0; kt < KT1; kt++) {
        uint32_t so = (uint32_t)s * S1;
#pragma unroll
        for (int ks = 0; ks < 2; ks++) {
            unsigned a[2][4];
#pragma unroll
            for (int mt = 0; mt < 2; mt++)
                ldsm4(a[mt], abase + so + mt * 1280 + ks * 32);
            uint32_t bb = sb + so + 10240 + ks * 8 * 288 + brow + bcol;
#pragma unroll
            for (int nt = 0; nt < 2; nt++) {
                uint32_t ba = bb + nt * 32;
                unsigned b0 = tf32r(lds32(ba)),        b1 = tf32r(lds32(ba + 4 * 288));
                unsigned c0 = tf32r(lds32(ba + 4608)), c1 = tf32r(lds32(ba + 4608 + 4 * 288));
#pragma unroll
                for (int mt = 0; mt < 2; mt++) {
                    mma8(acc1[mt][nt], a[mt], b0, b1);
                    mma8(acc3[mt][nt], a[mt], c0, c1);
                }
            }
        }
        int nk = kt + 2;
        if (nk < KT1) fill(fs, nk * 16);
        CPC();
        CPW1(); __syncthreads();
        s = (s == 2) ? 0 : s + 1;
        fs = (fs == 2) ? 0 : fs + 1;
    }
    CPW0();

    // epilogue: silu(y1)*y3 -> g_h[slot], pre-rounded to tf32
#pragma unroll
    for (int mt = 0; mt < 2; mt++) {
        int mloc = m_base + mt * 16 + (lane >> 2);
        int s_lo = rslot[mloc], s_hi = rslot[mloc + 8];
#pragma unroll
        for (int nt = 0; nt < 2; nt++) {
            int col = n0 + n_base + nt * 8 + 2 * (lane & 3);
            if (s_lo >= 0) {
                float* hp = g_h + (size_t)s_lo * HIDDEN + col;
                float a0 = acc1[mt][nt][0], a1 = acc1[mt][nt][1];
                hp[0] = rtf(a0 / (1.f + __expf(-a0)) * acc3[mt][nt][0]);
                hp[1] = rtf(a1 / (1.f + __expf(-a1)) * acc3[mt][nt][1]);
            }
            if (s_hi >= 0) {
                float* hp = g_h + (size_t)s_hi * HIDDEN + col;
                float a2 = acc1[mt][nt][2], a3 = acc1[mt][nt][3];
                hp[0] = rtf(a2 / (1.f + __expf(-a2)) * acc3[mt][nt][2]);
                hp[1] = rtf(a3 / (1.f + __expf(-a3)) * acc3[mt][nt][3]);
            }
        }
    }
}

// ============================================================================
// GEMM2: out += wt * (h @ w2).
// BM=128, BN=128, BK=16, 512 threads (16 warps, 32x32 warp tiles).
// stage: A 10240 + B 16x544 = 8704 -> 18944. 3 stages.
// ============================================================================
#define S2 18944
#define KT2 (HIDDEN / 16)

__global__ __launch_bounds__(512, 2)
void gemm2_k(const float* __restrict__ w2, float* __restrict__ out) {
    int e = blockIdx.z, Ne = g_cnt[e];
    int m0 = blockIdx.x * 128;
    if (m0 >= Ne) return;
    int n0 = blockIdx.y * 128;

    extern __shared__ __align__(128) char sm[];
    uint32_t sb = smem_u32(sm);
    __shared__ int rtok[128], rsl[128];
    __shared__ float rwt[128];

    int tid = threadIdx.x, warp = tid >> 5, lane = tid & 31;
    if (tid < 128) {
        int r = m0 + tid;
        if (r < Ne) { rtok[tid] = g_tok[e][r]; rsl[tid] = g_slotA[e][r]; rwt[tid] = g_wt[e][r]; }
        else        { rtok[tid] = -1; rsl[tid] = 0; rwt[tid] = 0.f; }
    }
    __syncthreads();

    int am = tid >> 2, aq = tid & 3;
    const float* asrc = g_h + (size_t)rsl[am] * HIDDEN + aq * 4;
    uint32_t adst = sb + am * 80 + aq * 16;
    int br = tid >> 5, bq = tid & 31;
    const float* bsrc = w2 + (size_t)e * HIDDEN * DIM + n0 + (size_t)br * DIM + bq * 4;
    uint32_t bdst = sb + 10240 + br * 544 + bq * 16;

    auto fill = [&](int s, int k0) {
        uint32_t so = (uint32_t)s * S2;
        CPA(adst + so, asrc + k0);
        CPA(bdst + so, bsrc + (size_t)k0 * DIM);
    };

    // ---- mma geometry: 4m x 4n warp grid, warp tile 32x32 ----
    int m_base = (warp >> 2) * 32, n_base = (warp & 3) * 32;
    int lrow = (lane & 7) + ((lane >> 3) & 1) * 8;
    uint32_t abase = sb + (m_base + lrow) * 80 + (lane >> 4) * 16;
    uint32_t bcol  = (uint32_t)(n_base + (lane >> 2)) * 4;
    uint32_t brow  = (uint32_t)(lane & 3) * 544;

    float acc[2][4][4];
#pragma unroll
    for (int a = 0; a < 2; a++)
#pragma unroll
        for (int b = 0; b < 4; b++)
#pragma unroll
            for (int c = 0; c < 4; c++) acc[a][b][c] = 0.f;

    fill(0, 0); CPC();
    fill(1, 16); CPC();
    CPW1(); __syncthreads();

    int s = 0, fs = 2;
    for (int kt = 0; kt < KT2; kt++) {
        uint32_t so = (uint32_t)s * S2;
#pragma unroll
        for (int ks = 0; ks < 2; ks++) {
            unsigned a[2][4];
#pragma unroll
            for (int mt = 0; mt < 2; mt++)
                ldsm4(a[mt], abase + so + mt * 1280 + ks * 32);
            uint32_t bb = sb + so + 10240 + ks * 8 * 544 + brow + bcol;
#pragma unroll
            for (int nt = 0; nt < 4; nt++) {
                uint32_t ba = bb + nt * 32;
                unsigned b0 = tf32r(lds32(ba)), b1 = tf32r(lds32(ba + 4 * 544));
#pragma unroll
                for (int mt = 0; mt < 2; mt++)
                    mma8(acc[mt][nt], a[mt], b0, b1);
            }
        }
        int nk = kt + 2;
        if (nk < KT2) fill(fs, nk * 16);
        CPC();
        CPW1(); __syncthreads();
        s = (s == 2) ? 0 : s + 1;
        fs = (fs == 2) ? 0 : fs + 1;
    }
    CPW0();

    // epilogue: out[token] += wt * acc
#pragma unroll
    for (int mt = 0; mt < 2; mt++) {
        int mloc = m_base + mt * 16 + (lane >> 2);
        int t_lo = rtok[mloc], t_hi = rtok[mloc + 8];
        float w_lo = rwt[mloc], w_hi = rwt[mloc + 8];
#pragma unroll
        for (int nt = 0; nt < 4; nt++) {
            int col = n0 + n_base + nt * 8 + 2 * (lane & 3);
            if (t_lo >= 0) {
                atomicAdd(&out[(size_t)t_lo * DIM + col],     w_lo * acc[mt][nt][0]);
                atomicAdd(&out[(size_t)t_lo * DIM + col + 1], w_lo * acc[mt][nt][1]);
            }
            if (t_hi >= 0) {
                atomicAdd(&out[(size_t)t_hi * DIM + col],     w_hi * acc[mt][nt][2]);
                atomicAdd(&out[(size_t)t_hi * DIM + col + 1], w_hi * acc[mt][nt][3]);
            }
        }
    }
}

// ---------------- launch ----------------
extern "C" void kernel_launch(void* const* d_in, const int* in_sizes, int n_in,
                              void* d_out, int out_size) {
    const float* x  = (const float*)d_in[0];
    const float* Wg = (const float*)d_in[1];
    const float* w1 = (const float*)d_in[2];
    const float* w3 = (const float*)d_in[3];
    const float* w2 = (const float*)d_in[4];
    float* out = (float*)d_out;

    cudaFuncSetAttribute(gemm1_k, cudaFuncAttributeMaxDynamicSharedMemorySize, 3 * S1);
    cudaFuncSetAttribute(gemm2_k, cudaFuncAttributeMaxDynamicSharedMemorySize, 3 * S2);

    zero_kernel<<<1024, 256>>>(out, out_size);
    round_x_kernel<<<1024, 256>>>(x);
    gate_kernel<<<NTOK / 8, 256>>>(x, Wg);

    dim3 g1(NTOK / 128, HIDDEN / 64, NE_);   // (16, 112, 8)
    gemm1_k<<<g1, 512, 3 * S1>>>(w1, w3);

    dim3 g2(NTOK / 128, DIM / 128, NE_);     // (16, 16, 8)
    gemm2_k<<<g2, 512, 3 * S2>>>(w2, out);
}